// round 13
// baseline (speedup 1.0000x reference)
#include <cuda_runtime.h>

// ---------------------------------------------------------------------------
// Device scratch. Margin over N=4096, E=65536, n=128, D=64.
// ---------------------------------------------------------------------------
#define SCRATCH_ELEMS (1 << 20)
#define MAX_N 8192
#define ROW_CAP 384
#define OFLOW_CAP 65536

__device__ float g_a[SCRATCH_ELEMS];
__device__ float g_c[SCRATCH_ELEMS];
__device__ int g_count[MAX_N];
__device__ int g_elist[MAX_N * ROW_CAP];   // packed (lj << 24) | e
__device__ int g_oflow_cnt;
__device__ int g_oflow[OFLOW_CAP];

// ---------------------------------------------------------------------------
// Kernel 1: per-node projections (best measured config: 7.6-7.9us).
// a[i][d] = sum_k x[i][k]*W[d][k] + b[d] ;  c[i][d] = sum_k x[i][k]*W[d][64+k]
// Block 0 additionally zeroes the edge-bucket counters (free; ordered before
// place_kernel by stream order).
// ---------------------------------------------------------------------------
#define PROJ_BN 16
#define WS_STRIDE 132

__global__ void proj64_kernel(const float* __restrict__ x,
                              const float* __restrict__ W,
                              const float* __restrict__ bias,
                              int N) {
    __shared__ __align__(16) float ws[64 * WS_STRIDE];
    __shared__ __align__(16) float xs[PROJ_BN][64];

    int tid = threadIdx.x;  // 256

    if (blockIdx.x == 0) {
        for (int i = tid; i < N && i < MAX_N; i += 256) g_count[i] = 0;
        if (tid == 0) g_oflow_cnt = 0;
    }

    // Stage W: 2048 float4 over 256 threads -> 8 LDG.128 each.
    const float4* __restrict__ W4 = reinterpret_cast<const float4*>(W);
#pragma unroll
    for (int i4 = tid; i4 < 64 * 32; i4 += 256) {
        int r = i4 >> 5;
        int c4 = i4 & 31;
        *reinterpret_cast<float4*>(&ws[r * WS_STRIDE + c4 * 4]) = W4[i4];
    }

    int base = blockIdx.x * PROJ_BN;
    const float4* __restrict__ x4 = reinterpret_cast<const float4*>(x);
#pragma unroll
    for (int i4 = tid; i4 < PROJ_BN * 16; i4 += 256) {
        int nd = i4 >> 4, k4 = i4 & 15;
        int node = base + nd;
        float4 v = (node < N) ? x4[(size_t)node * 16 + k4]
                              : make_float4(0.f, 0.f, 0.f, 0.f);
        *reinterpret_cast<float4*>(&xs[nd][k4 * 4]) = v;
    }
    __syncthreads();

    int d = tid & 63;
    int ty = tid >> 6;  // 0..3 -> nodes ty*4 .. ty*4+3

    const float4* __restrict__ wrowA =
        reinterpret_cast<const float4*>(&ws[d * WS_STRIDE]);
    const float4* __restrict__ wrowC =
        reinterpret_cast<const float4*>(&ws[d * WS_STRIDE + 64]);

    float accA[4] = {0.f, 0.f, 0.f, 0.f};
    float accC[4] = {0.f, 0.f, 0.f, 0.f};

#pragma unroll
    for (int k4 = 0; k4 < 16; k4++) {
        float4 wA = wrowA[k4];
        float4 wC = wrowC[k4];
#pragma unroll
        for (int u = 0; u < 4; u++) {
            float4 v = *reinterpret_cast<const float4*>(&xs[ty * 4 + u][k4 * 4]);
            accA[u] = fmaf(v.x, wA.x, accA[u]); accA[u] = fmaf(v.y, wA.y, accA[u]);
            accA[u] = fmaf(v.z, wA.z, accA[u]); accA[u] = fmaf(v.w, wA.w, accA[u]);
            accC[u] = fmaf(v.x, wC.x, accC[u]); accC[u] = fmaf(v.y, wC.y, accC[u]);
            accC[u] = fmaf(v.z, wC.z, accC[u]); accC[u] = fmaf(v.w, wC.w, accC[u]);
        }
    }

    float bv = bias[d];
#pragma unroll
    for (int u = 0; u < 4; u++) {
        int node = base + ty * 4 + u;
        if (node < N) {
            g_a[(size_t)node * 64 + d] = accA[u] + bv;
            g_c[(size_t)node * 64 + d] = accC[u];
        }
    }
}

// ---------------------------------------------------------------------------
// Kernel 2: bucket edges by output row (= src). Entry = (lj << 24) | e.
// Overflow (slot >= ROW_CAP) goes to a global overflow list.
// ---------------------------------------------------------------------------
__global__ void place_kernel(const int* __restrict__ edge_index, int E, int n) {
    int e = blockIdx.x * blockDim.x + threadIdx.x;
    if (e >= E) return;
    int src = edge_index[e];
    int dst = edge_index[E + e];
    int g = src / n;
    int lj = dst - g * n;
    int slot = atomicAdd(&g_count[src], 1);
    if (slot < ROW_CAP) {
        g_elist[src * ROW_CAP + slot] = (lj << 24) | e;
    } else {
        int o = atomicAdd(&g_oflow_cnt, 1);
        if (o < OFLOW_CAP) g_oflow[o] = e;
    }
}

// ---------------------------------------------------------------------------
// Kernel 3: dense fill + edge-overwrite epilogue.
// Pass 1 (identical to proven fill1): out[gi,j,:] = a[gi] + c[g*n+j], __stcs.
// Pass 2 (after barrier): for each distinct lj in this row's edge list, the
// leader entry re-stores out[gi,lj,:] = a + c + sum(attrs). Overwrite, not
// RMW: no atomics, no out reads. Typical cnt ~16 -> epilogue is tiny.
// Overflow edges (rare/never) are applied with global atomics at the end.
// ---------------------------------------------------------------------------
__global__ void fill_kernel(const int* __restrict__ edge_index,
                            const float4* __restrict__ edge_attr,
                            float4* __restrict__ out,
                            int E, int n, int D4) {
    __shared__ int s_edge[ROW_CAP];
    __shared__ int s_cnt;

    int gi = blockIdx.x;
    int g = gi / n;
    int tid = threadIdx.x;  // 256

    if (tid == 0) {
        int c = g_count[gi];
        s_cnt = (c < ROW_CAP) ? c : ROW_CAP;
    }
    __syncthreads();
    int cnt = s_cnt;
    for (int t = tid; t < cnt; t += 256) s_edge[t] = g_elist[gi * ROW_CAP + t];

    const float4* __restrict__ a4 =
        reinterpret_cast<const float4*>(g_a) + (size_t)gi * D4;
    const float4* __restrict__ cbase =
        reinterpret_cast<const float4*>(g_c) + (size_t)g * n * D4;

    int d4m = tid % D4;
    int j0 = tid / D4;
    int jstep = 256 / D4;

    float4 av = a4[d4m];
    float4* __restrict__ orow = out + (size_t)gi * n * D4;

    // Pass 1: pure broadcast fill (proven store-bound configuration).
    for (int j = j0; j < n; j += jstep) {
        float4 cv = cbase[(size_t)j * D4 + d4m];
        float4 o;
        o.x = av.x + cv.x;
        o.y = av.y + cv.y;
        o.z = av.z + cv.z;
        o.w = av.w + cv.w;
        __stcs(&orow[(size_t)j * D4 + d4m], o);
    }

    __syncthreads();  // order pass-1 stores before epilogue overwrites

    // Pass 2: edge overwrite. Thread handles (entry i, component d4).
    for (int idx = tid; idx < cnt * D4; idx += 256) {
        int i = idx / D4;
        int d4 = idx % D4;
        unsigned pki = (unsigned)s_edge[i];
        int lj = (int)(pki >> 24);
        // Leader check: no earlier entry with the same lj.
        bool leader = true;
        for (int k = 0; k < i; k++) {
            if (((unsigned)s_edge[k] >> 24) == (unsigned)lj) { leader = false; break; }
        }
        if (!leader) continue;
        int e0 = (int)(pki & 0xFFFFFF);
        float4 acc = edge_attr[(size_t)e0 * D4 + d4];
        for (int k = i + 1; k < cnt; k++) {
            unsigned pkk = (unsigned)s_edge[k];
            if ((pkk >> 24) == (unsigned)lj) {
                float4 v = edge_attr[(size_t)(pkk & 0xFFFFFF) * D4 + d4];
                acc.x += v.x; acc.y += v.y; acc.z += v.z; acc.w += v.w;
            }
        }
        float4 a = a4[d4];
        float4 cv = cbase[(size_t)lj * D4 + d4];
        float4 o;
        o.x = a.x + cv.x + acc.x;
        o.y = a.y + cv.y + acc.y;
        o.z = a.z + cv.z + acc.z;
        o.w = a.w + cv.w + acc.w;
        orow[(size_t)lj * D4 + d4] = o;
    }

    // Overflow handling (normal case: one broadcast load, no work).
    int ocnt = g_oflow_cnt;
    if (ocnt > 0) {
        if (ocnt > OFLOW_CAP) ocnt = OFLOW_CAP;
        __syncthreads();  // order epilogue stores before overflow atomics
        for (int t = tid; t < ocnt * D4; t += 256) {
            int e = g_oflow[t / D4];
            int d4 = t % D4;
            if (edge_index[e] != gi) continue;
            int dst = edge_index[E + e];
            int lj = dst - g * n;
            float4 v = edge_attr[(size_t)e * D4 + d4];
            float* p = reinterpret_cast<float*>(&orow[(size_t)lj * D4 + d4]);
            atomicAdd(p + 0, v.x);
            atomicAdd(p + 1, v.y);
            atomicAdd(p + 2, v.z);
            atomicAdd(p + 3, v.w);
        }
    }
}

// ---------------------------------------------------------------------------
// Legacy split path (shapes outside the fused guards).
// ---------------------------------------------------------------------------
__global__ void fill1_kernel(float4* __restrict__ out, int n, int D4) {
    int gi = blockIdx.x;
    int g = gi / n;
    const float4* __restrict__ a4 =
        reinterpret_cast<const float4*>(g_a) + (size_t)gi * D4;
    const float4* __restrict__ cbase =
        reinterpret_cast<const float4*>(g_c) + (size_t)g * n * D4;
    int d4 = threadIdx.x % D4;
    int j0 = threadIdx.x / D4;
    int jstep = blockDim.x / D4;
    float4 av = a4[d4];
    float4* __restrict__ orow = out + (size_t)gi * n * D4;
    for (int j = j0; j < n; j += jstep) {
        float4 cv = cbase[(size_t)j * D4 + d4];
        float4 o;
        o.x = av.x + cv.x;
        o.y = av.y + cv.y;
        o.z = av.z + cv.z;
        o.w = av.w + cv.w;
        __stcs(&orow[(size_t)j * D4 + d4], o);
    }
}

__global__ void scatter_kernel(const int* __restrict__ edge_index,
                               const float4* __restrict__ edge_attr,
                               float4* __restrict__ out,
                               int E, int n, int D4) {
    int t = blockIdx.x * blockDim.x + threadIdx.x;
    int e = t / D4;
    int d4 = t % D4;
    if (e >= E) return;
    int src = edge_index[e];
    int dst = edge_index[E + e];
    int g = src / n;
    int lj = dst - g * n;
    float4 v = edge_attr[(size_t)e * D4 + d4];
    atomicAdd(&out[((size_t)src * n + lj) * D4 + d4], v);
}

// ---------------------------------------------------------------------------
extern "C" void kernel_launch(void* const* d_in, const int* in_sizes, int n_in,
                              void* d_out, int out_size) {
    const float* x = (const float*)d_in[0];
    const int* edge_index = (const int*)d_in[1];
    const float* edge_attr = (const float*)d_in[2];
    // d_in[3] = batch: implied by src / n for equal-sized graphs
    // d_in[4] = token_index: unused (it enumerates all (i,j) pairs in order)
    const float* W = (const float*)d_in[5];
    const float* b = (const float*)d_in[6];

    int D = in_sizes[6];     // 64
    int N = in_sizes[3];     // 4096 nodes total
    int E = in_sizes[2] / D; // 65536 edges
    int T = in_sizes[4] / 2; // 524288 pairs
    int n = T / N;           // 128 nodes per graph
    int D4 = D / 4;          // 16 float4 per feature row

    float* out = (float*)d_out;

    bool fused = (n <= 256) && (N <= MAX_N) && (E < (1 << 24)) && (D4 <= 16);

    // 1. per-node projections (+ counter zeroing in block 0)
    {
        int grid = (N + PROJ_BN - 1) / PROJ_BN;
        proj64_kernel<<<grid, 256>>>(x, W, b, N);
    }

    if (fused) {
        // 2. bucket edges by output row
        place_kernel<<<(E + 255) / 256, 256>>>(edge_index, E, n);
        // 3. dense fill + per-row edge-overwrite epilogue (no atomics)
        fill_kernel<<<N, 256>>>(edge_index, (const float4*)edge_attr,
                                (float4*)out, E, n, D4);
    } else {
        fill1_kernel<<<N, 256>>>((float4*)out, n, D4);
        long long work = (long long)E * D4;
        scatter_kernel<<<(int)((work + 255) / 256), 256>>>(
            edge_index, (const float4*)edge_attr, (float4*)out, E, n, D4);
    }
}

// round 14
// speedup vs baseline: 1.3368x; 1.3368x over previous
#include <cuda_runtime.h>

// ---------------------------------------------------------------------------
// Device scratch. Sized with margin over N=4096, D=64.
// ---------------------------------------------------------------------------
#define SCRATCH_ELEMS (1 << 20)
__device__ float g_a[SCRATCH_ELEMS];
__device__ float g_c[SCRATCH_ELEMS];

// ---------------------------------------------------------------------------
// Kernel 1: per-node projections (best measured config: 7.65us).
// a[i][d] = sum_k x[i][k]*W[d][k] + b[d] ;  c[i][d] = sum_k x[i][k]*W[d][64+k]
// W [64,128] staged via LDG.128 into smem, row stride 132 (16B aligned,
// lanes d hit banks (d+k) mod 32 -> conflict-free LDS.128 compute loop).
// PROJ_BN=16 nodes/block, 256 threads, 4 nodes per thread.
// ---------------------------------------------------------------------------
#define PROJ_BN 16
#define WS_STRIDE 132

__global__ void proj64_kernel(const float* __restrict__ x,
                              const float* __restrict__ W,
                              const float* __restrict__ bias,
                              int N) {
    __shared__ __align__(16) float ws[64 * WS_STRIDE];
    __shared__ __align__(16) float xs[PROJ_BN][64];

    int tid = threadIdx.x;  // 256

    // Stage W: 2048 float4 over 256 threads -> 8 LDG.128 each.
    const float4* __restrict__ W4 = reinterpret_cast<const float4*>(W);
#pragma unroll
    for (int i4 = tid; i4 < 64 * 32; i4 += 256) {
        int r = i4 >> 5;
        int c4 = i4 & 31;
        *reinterpret_cast<float4*>(&ws[r * WS_STRIDE + c4 * 4]) = W4[i4];
    }

    int base = blockIdx.x * PROJ_BN;
    // Stage x tile: PROJ_BN*16 = 256 float4 -> 1 per thread.
    const float4* __restrict__ x4 = reinterpret_cast<const float4*>(x);
#pragma unroll
    for (int i4 = tid; i4 < PROJ_BN * 16; i4 += 256) {
        int nd = i4 >> 4, k4 = i4 & 15;
        int node = base + nd;
        float4 v = (node < N) ? x4[(size_t)node * 16 + k4]
                              : make_float4(0.f, 0.f, 0.f, 0.f);
        *reinterpret_cast<float4*>(&xs[nd][k4 * 4]) = v;
    }
    __syncthreads();

    int d = tid & 63;
    int ty = tid >> 6;  // 0..3 -> nodes ty*4 .. ty*4+3

    const float4* __restrict__ wrowA =
        reinterpret_cast<const float4*>(&ws[d * WS_STRIDE]);
    const float4* __restrict__ wrowC =
        reinterpret_cast<const float4*>(&ws[d * WS_STRIDE + 64]);

    float accA[4] = {0.f, 0.f, 0.f, 0.f};
    float accC[4] = {0.f, 0.f, 0.f, 0.f};

#pragma unroll
    for (int k4 = 0; k4 < 16; k4++) {
        float4 wA = wrowA[k4];
        float4 wC = wrowC[k4];
#pragma unroll
        for (int u = 0; u < 4; u++) {
            float4 v = *reinterpret_cast<const float4*>(&xs[ty * 4 + u][k4 * 4]);
            accA[u] = fmaf(v.x, wA.x, accA[u]); accA[u] = fmaf(v.y, wA.y, accA[u]);
            accA[u] = fmaf(v.z, wA.z, accA[u]); accA[u] = fmaf(v.w, wA.w, accA[u]);
            accC[u] = fmaf(v.x, wC.x, accC[u]); accC[u] = fmaf(v.y, wC.y, accC[u]);
            accC[u] = fmaf(v.z, wC.z, accC[u]); accC[u] = fmaf(v.w, wC.w, accC[u]);
        }
    }

    float bv = bias[d];
#pragma unroll
    for (int u = 0; u < 4; u++) {
        int node = base + ty * 4 + u;
        if (node < N) {
            g_a[(size_t)node * 64 + d] = accA[u] + bv;
            g_c[(size_t)node * 64 + d] = accC[u];
        }
    }
}

// ---------------------------------------------------------------------------
// Kernel 2: dense fill, one row per block (best measured configuration).
// out[gi, j, :] = a[gi] + c[g*n + j].
// __stcs (evict-first) streaming stores: the single biggest measured win
// (-4us) — the 128 MB write-once output must not thrash L2.
// ---------------------------------------------------------------------------
__global__ void fill_kernel(float4* __restrict__ out, int n, int D4) {
    int gi = blockIdx.x;
    int g = gi / n;

    const float4* __restrict__ a4 =
        reinterpret_cast<const float4*>(g_a) + (size_t)gi * D4;
    const float4* __restrict__ cbase =
        reinterpret_cast<const float4*>(g_c) + (size_t)g * n * D4;

    int d4 = threadIdx.x % D4;
    int j0 = threadIdx.x / D4;
    int jstep = blockDim.x / D4;

    float4 av = a4[d4];
    float4* __restrict__ orow = out + (size_t)gi * n * D4;

    for (int j = j0; j < n; j += jstep) {
        float4 cv = cbase[(size_t)j * D4 + d4];
        float4 o;
        o.x = av.x + cv.x;
        o.y = av.y + cv.y;
        o.z = av.z + cv.z;
        o.w = av.w + cv.w;
        __stcs(&orow[(size_t)j * D4 + d4], o);
    }
}

// ---------------------------------------------------------------------------
// Kernel 3: edge scatter-add. out[src, dst - g*n, :] += attr[e, :]
// (g*n + li == src for equal-sized graphs; g = src / n.)
// 128-bit atomicAdd (native REDG.128 on sm_90+), at its spread-address
// throughput floor. edge_attr is read exactly once -> __ldcs streaming hint.
// ---------------------------------------------------------------------------
__global__ void scatter_kernel(const int* __restrict__ edge_index,
                               const float4* __restrict__ edge_attr,
                               float4* __restrict__ out,
                               int E, int n, int D4) {
    int t = blockIdx.x * blockDim.x + threadIdx.x;
    int e = t / D4;
    int d4 = t % D4;
    if (e >= E) return;

    int src = edge_index[e];
    int dst = edge_index[E + e];
    int g = src / n;
    int lj = dst - g * n;

    float4 v = __ldcs(&edge_attr[(size_t)e * D4 + d4]);
    atomicAdd(&out[((size_t)src * n + lj) * D4 + d4], v);
}

// ---------------------------------------------------------------------------
extern "C" void kernel_launch(void* const* d_in, const int* in_sizes, int n_in,
                              void* d_out, int out_size) {
    const float* x = (const float*)d_in[0];
    const int* edge_index = (const int*)d_in[1];
    const float* edge_attr = (const float*)d_in[2];
    // d_in[3] = batch: implied by src / n for equal-sized graphs
    // d_in[4] = token_index: unused (it enumerates all (i,j) pairs in order)
    const float* W = (const float*)d_in[5];
    const float* b = (const float*)d_in[6];

    int D = in_sizes[6];     // 64
    int N = in_sizes[3];     // 4096 nodes total
    int E = in_sizes[2] / D; // 65536 edges
    int T = in_sizes[4] / 2; // 524288 pairs
    int n = T / N;           // 128 nodes per graph
    int D4 = D / 4;          // 16 float4 per feature row

    float* out = (float*)d_out;

    // 1. per-node projections (decomposed Linear: pair GEMVs -> 2 node GEMMs)
    {
        int grid = (N + PROJ_BN - 1) / PROJ_BN;
        proj64_kernel<<<grid, 256>>>(x, W, b, N);
    }

    // 2. dense broadcast fill (writes the 128 MiB output exactly once)
    fill_kernel<<<N, 256>>>((float4*)out, n, D4);

    // 3. edge feature scatter-add
    {
        long long work = (long long)E * D4;
        scatter_kernel<<<(int)((work + 255) / 256), 256>>>(
            edge_index, (const float4*)edge_attr, (float4*)out, E, n, D4);
    }
}